// round 15
// baseline (speedup 1.0000x reference)
#include <cuda_runtime.h>
#include <cuda_bf16.h>
#include <cstdint>

typedef unsigned int u32;
typedef unsigned long long u64;

// Problem constants
#define B_ROWS 16384
#define DIM    768
#define ATTRS  51
#define NPAD   64
#define BN_EPS 1e-5f
#define GRID_M 128            // 16384 / 128 rows per CTA
#define NKS    48             // 768 / 16 k-steps
#define BP_U4  12288          // 48*8*32 uint4 entries {hi0,hi1,lo0,lo1}
#define SMEM_DYN 196608       // BP_U4 * 16 bytes
#define NJ     8              // wc1 j-splits
#define JCH    (DIM / NJ)     // 96 j's per wc1 block

// -------- device scratch --------
__device__ float g_wcp[NJ * NPAD * DIM];         // [q][a][k] j-partials (1.5 MB)
__device__ __align__(16) u32 g_bp[4 * BP_U4];    // packed B frags, uint4-interleaved
__device__ float g_z[B_ROWS * NPAD];             // logits (bias-free, padded)
__device__ float g_psum[GRID_M * NPAD];
__device__ float g_psq[GRID_M * NPAD];
__device__ float g_a[NPAD];                      // rstd*gamma
__device__ float g_b[NPAD];                      // beta - mean*rstd*gamma

// pack bf16x2, memory order (lo,hi)
__device__ __forceinline__ u32 bf16x2(float lo, float hi) {
    u32 r; asm("cvt.rn.bf16x2.f32 %0, %1, %2;" : "=r"(r) : "f"(hi), "f"(lo)); return r;
}
// split a float2 into bf16x2 hi + bf16x2 lo (residual)
__device__ __forceinline__ void split2(float2 v, u32& h, u32& l) {
    h = bf16x2(v.x, v.y);
    float f0 = __uint_as_float(h << 16);
    float f1 = __uint_as_float(h & 0xFFFF0000u);
    l = bf16x2(v.x - f0, v.y - f1);
}
// D += A(16x16 bf16) * B(16x8 bf16), fp32 accum
__device__ __forceinline__ void mma16816(float* c, const u32* a, u32 b0, u32 b1) {
    asm volatile(
        "mma.sync.aligned.m16n8k16.row.col.f32.bf16.bf16.f32 "
        "{%0,%1,%2,%3}, {%4,%5,%6,%7}, {%8,%9}, {%0,%1,%2,%3};"
        : "+f"(c[0]), "+f"(c[1]), "+f"(c[2]), "+f"(c[3])
        : "r"(a[0]), "r"(a[1]), "r"(a[2]), "r"(a[3]), "r"(b0), "r"(b1));
}
__device__ __forceinline__ u32 smem_u32(const void* p) {
    u32 a;
    asm("{ .reg .u64 t; cvta.to.shared.u64 t, %1; cvt.u32.u64 %0, t; }" : "=r"(a) : "l"(p));
    return a;
}
#define CP_ASYNC16(dst, src) \
    asm volatile("cp.async.cg.shared.global [%0], [%1], 16;" :: "r"(dst), "l"(src) : "memory")
#define CP_COMMIT() asm volatile("cp.async.commit_group;" ::: "memory")
#define CP_WAIT(n)  asm volatile("cp.async.wait_group %0;" :: "n"(n) : "memory")

// ============================================================
// wc1: j-partial Wc[a][k] over JCH j's, 8 attrs per block.
// grid (6 k-blocks, 8 a-groups, NJ) = 384 blocks, 128 thr
// (~10 warps/SM: latency hidden; W_embed L2 traffic 18MB).
// ============================================================
__global__ __launch_bounds__(128) void wc1_kernel(const float* __restrict__ W_embed,
                                                  const float* __restrict__ W_attr) {
    __shared__ __align__(16) float s_wi[JCH * 8];   // [j][aa] interleaved
    const int k  = blockIdx.x * 128 + threadIdx.x;
    const int a0 = blockIdx.y * 8;
    const int j0 = blockIdx.z * JCH;

    for (int i = threadIdx.x; i < JCH * 8; i += 128) {
        int aa = i & 7, j = i >> 3;
        int a  = a0 + aa;
        s_wi[i] = (a < ATTRS) ? W_attr[a * DIM + j0 + j] : 0.0f;
    }
    __syncthreads();

    float acc[8];
#pragma unroll
    for (int i = 0; i < 8; ++i) acc[i] = 0.0f;

#pragma unroll 8
    for (int j = 0; j < JCH; ++j) {
        float we = W_embed[(size_t)(j0 + j) * DIM + k];   // coalesced, L2-hot
        const float4* wrow = (const float4*)&s_wi[j * 8];
        float4 w0 = wrow[0], w1 = wrow[1];
        acc[0] = fmaf(w0.x, we, acc[0]);   acc[1] = fmaf(w0.y, we, acc[1]);
        acc[2] = fmaf(w0.z, we, acc[2]);   acc[3] = fmaf(w0.w, we, acc[3]);
        acc[4] = fmaf(w1.x, we, acc[4]);   acc[5] = fmaf(w1.y, we, acc[5]);
        acc[6] = fmaf(w1.z, we, acc[6]);   acc[7] = fmaf(w1.w, we, acc[7]);
    }
    float* dst = g_wcp + (size_t)blockIdx.z * NPAD * DIM;
#pragma unroll
    for (int aa = 0; aa < 8; ++aa)
        dst[(a0 + aa) * DIM + k] = acc[aa];
}

// ============================================================
// wc2: combine NJ partials, split bf16 hi/lo, scatter into
// fused uint4 B-fragment layout: entry (ks,nt,lane) = {hi0,hi1,lo0,lo1}
// ============================================================
__global__ __launch_bounds__(256) void wc2_kernel() {
    int idx = blockIdx.x * 256 + threadIdx.x;     // 0..24575
    if (idx >= NPAD * DIM / 2) return;
    int n  = idx / 384;                           // 0..63
    int kp = idx - n * 384;
    int k  = kp * 2;
    size_t i0 = (size_t)n * DIM + k;
    const size_t S = (size_t)NPAD * DIM;
    float s0 = 0.f, s1 = 0.f;
#pragma unroll
    for (int q = 0; q < NJ; ++q) {
        s0 += g_wcp[q * S + i0];
        s1 += g_wcp[q * S + i0 + 1];
    }
    u32 h = bf16x2(s0, s1);
    float f0 = __uint_as_float(h << 16);
    float f1 = __uint_as_float(h & 0xFFFF0000u);
    u32 l = bf16x2(s0 - f0, s1 - f1);

    int ks = k >> 4;
    int hh = (k >> 3) & 1;
    int t  = (n & 7) * 4 + ((k & 7) >> 1);
    int nt = n >> 3;
    int o4 = ((ks * 8 + nt) * 32 + t) * 4;
    g_bp[o4 + hh]     = h;
    g_bp[o4 + 2 + hh] = l;
}

// ============================================================
// GEMM: z = x @ Wc^T via mma.sync bf16 hi/lo split (3 products).
// grid 128, 256 threads = 8 warps; warp w owns rows [w*16,+16).
// B staged via cp.async in 2 halves overlapped with compute.
// A from gmem fp32 at prefetch depth 4, split in registers.
// ============================================================
extern __shared__ __align__(16) char dsm[];

// one k-step of the mainloop
__device__ __forceinline__ void kstep(int ks, float2 (&pf)[4][4],
                                      const float* xr0, const float* xr8,
                                      const uint4* sb, int lane,
                                      float (&acc)[8][4]) {
    float2 c0 = pf[ks & 3][0], c1 = pf[ks & 3][1];
    float2 c2 = pf[ks & 3][2], c3 = pf[ks & 3][3];
    if (ks + 4 < NKS) {
        int kc = (ks + 4) * 16;
        pf[ks & 3][0] = *(const float2*)(xr0 + kc);
        pf[ks & 3][1] = *(const float2*)(xr0 + kc + 8);
        pf[ks & 3][2] = *(const float2*)(xr8 + kc);
        pf[ks & 3][3] = *(const float2*)(xr8 + kc + 8);
    }
    u32 ah[4], al[4];
    split2(c0, ah[0], al[0]);
    split2(c2, ah[1], al[1]);
    split2(c1, ah[2], al[2]);
    split2(c3, ah[3], al[3]);
    const uint4* bp = sb + ks * 256 + lane;
#pragma unroll
    for (int nt = 0; nt < 8; ++nt) {
        uint4 b = bp[nt * 32];
        mma16816(acc[nt], ah, b.x, b.y);
        mma16816(acc[nt], ah, b.z, b.w);
        mma16816(acc[nt], al, b.x, b.y);
    }
}

__global__ __launch_bounds__(256) void gemm_kernel(const float* __restrict__ x) {
    const int tid  = threadIdx.x;
    const int warp = tid >> 5, lane = tid & 31;

    // ---- stage packed B via cp.async: 2 halves of 6144 uint4 ----
    {
        const u32 sbase = smem_u32(dsm);
        const uint4* src = (const uint4*)g_bp;
#pragma unroll
        for (int i = 0; i < 24; ++i) {
            int idx = tid + i * 256;
            CP_ASYNC16(sbase + idx * 16, src + idx);
        }
        CP_COMMIT();
#pragma unroll
        for (int i = 0; i < 24; ++i) {
            int idx = 6144 + tid + i * 256;
            CP_ASYNC16(sbase + idx * 16, src + idx);
        }
        CP_COMMIT();
    }
    const uint4* sb = (const uint4*)dsm;   // [(ks*8+nt)*32 + lane] = {hi0,hi1,lo0,lo1}

    const int r0 = blockIdx.x * 128 + warp * 16 + (lane >> 2);
    const float* xr0 = x + (size_t)r0 * DIM + (lane & 3) * 2;
    const float* xr8 = xr0 + 8 * DIM;

    float acc[8][4];
#pragma unroll
    for (int i = 0; i < 8; ++i)
#pragma unroll
        for (int j = 0; j < 4; ++j) acc[i][j] = 0.0f;

    // A fragment prefetch, depth 4
    float2 pf[4][4];
#pragma unroll
    for (int p = 0; p < 4; ++p) {
        int kc = p * 16;
        pf[p][0] = *(const float2*)(xr0 + kc);
        pf[p][1] = *(const float2*)(xr0 + kc + 8);
        pf[p][2] = *(const float2*)(xr8 + kc);
        pf[p][3] = *(const float2*)(xr8 + kc + 8);
    }

    CP_WAIT(1);            // first half of B resident
    __syncthreads();

#pragma unroll 4
    for (int ks = 0; ks < 24; ++ks)
        kstep(ks, pf, xr0, xr8, sb, lane, acc);

    CP_WAIT(0);            // second half of B resident
    __syncthreads();

#pragma unroll 4
    for (int ks = 24; ks < NKS; ++ks)
        kstep(ks, pf, xr0, xr8, sb, lane, acc);

    // ---- epilogue: store z + BN partials (reuse smem) ----
    __syncthreads();
    float* ssum = (float*)dsm;
    float* ssq  = ssum + NPAD;
    if (tid < 2 * NPAD) ssum[tid] = 0.0f;
    __syncthreads();

    float* zr = g_z + (size_t)r0 * NPAD;
#pragma unroll
    for (int nt = 0; nt < 8; ++nt) {
        int n0 = nt * 8 + (lane & 3) * 2;
        *(float2*)(zr + n0)            = make_float2(acc[nt][0], acc[nt][1]);
        *(float2*)(zr + 8 * NPAD + n0) = make_float2(acc[nt][2], acc[nt][3]);
        float s0 = acc[nt][0] + acc[nt][2];
        float s1 = acc[nt][1] + acc[nt][3];
        float q0 = fmaf(acc[nt][0], acc[nt][0], acc[nt][2] * acc[nt][2]);
        float q1 = fmaf(acc[nt][1], acc[nt][1], acc[nt][3] * acc[nt][3]);
#pragma unroll
        for (int m = 4; m <= 16; m <<= 1) {
            s0 += __shfl_xor_sync(0xffffffffu, s0, m);
            s1 += __shfl_xor_sync(0xffffffffu, s1, m);
            q0 += __shfl_xor_sync(0xffffffffu, q0, m);
            q1 += __shfl_xor_sync(0xffffffffu, q1, m);
        }
        if (lane < 4) {
            atomicAdd(&ssum[n0], s0);     atomicAdd(&ssum[n0 + 1], s1);
            atomicAdd(&ssq[n0], q0);      atomicAdd(&ssq[n0 + 1], q1);
        }
    }
    __syncthreads();
    if (tid < NPAD) {
        g_psum[blockIdx.x * NPAD + tid] = ssum[tid];
        g_psq[blockIdx.x * NPAD + tid]  = ssq[tid];
    }
}

// ============================================================
// stats: one block per column n (64 blocks, 128 threads)
// ============================================================
__global__ __launch_bounds__(128) void stats_kernel(const float* __restrict__ gamma,
                                                    const float* __restrict__ beta) {
    __shared__ float ss[4], sq[4];
    const int n = blockIdx.x;           // 0..63
    const int t = threadIdx.x;          // 0..127
    float s = g_psum[t * NPAD + n];
    float q = g_psq[t * NPAD + n];
#pragma unroll
    for (int m = 16; m >= 1; m >>= 1) {
        s += __shfl_xor_sync(0xffffffffu, s, m);
        q += __shfl_xor_sync(0xffffffffu, q, m);
    }
    if ((t & 31) == 0) { ss[t >> 5] = s; sq[t >> 5] = q; }
    __syncthreads();
    if (t == 0) {
        float S = ss[0] + ss[1] + ss[2] + ss[3];
        float Q = sq[0] + sq[1] + sq[2] + sq[3];
        const float inv = 1.0f / (float)B_ROWS;
        float mean = S * inv;
        float var  = Q * inv - mean * mean;
        float rstd = rsqrtf(var + BN_EPS);
        float gm = (n < ATTRS) ? gamma[n] : 0.0f;
        float bt = (n < ATTRS) ? beta[n]  : 0.0f;
        float a = rstd * gm;
        g_a[n] = a;
        g_b[n] = bt - mean * a;
    }
}

// ============================================================
// norm: y = z*a[n] + b[n] -> d_out [B,51]
// one thread per quad: 13 quads cover 51 cols (last quad = 3).
// 16384 * 13 = 212992 = 416 * 512 threads exactly.
// ============================================================
__global__ __launch_bounds__(512) void norm_kernel(float* __restrict__ out) {
    const u32 idx = blockIdx.x * 512 + threadIdx.x;
    const u32 row = idx / 13u;
    const u32 q   = idx - row * 13u;
    const int n0  = q * 4;
    float4 z = *(const float4*)(g_z + (size_t)row * NPAD + n0);
    float* o = out + (size_t)row * ATTRS + n0;
    o[0] = fmaf(z.x, g_a[n0],     g_b[n0]);
    o[1] = fmaf(z.y, g_a[n0 + 1], g_b[n0 + 1]);
    o[2] = fmaf(z.z, g_a[n0 + 2], g_b[n0 + 2]);
    if (q < 12) o[3] = fmaf(z.w, g_a[n0 + 3], g_b[n0 + 3]);
}

// ============================================================
extern "C" void kernel_launch(void* const* d_in, const int* in_sizes, int n_in,
                              void* d_out, int out_size) {
    const float* x       = (const float*)d_in[0];
    const float* W_embed = (const float*)d_in[1];
    // d_in[2] = b_embed  (cancelled exactly by BatchNorm mean-subtraction)
    const float* W_attr  = (const float*)d_in[3];
    // d_in[4] = b_attr   (cancelled exactly by BatchNorm mean-subtraction)
    const float* gamma   = (const float*)d_in[5];
    const float* beta    = (const float*)d_in[6];
    float* out = (float*)d_out;

    cudaFuncSetAttribute(gemm_kernel, cudaFuncAttributeMaxDynamicSharedMemorySize, SMEM_DYN);

    wc1_kernel<<<dim3(6, 8, NJ), 128>>>(W_embed, W_attr);
    wc2_kernel<<<96, 256>>>();
    gemm_kernel<<<GRID_M, 256, SMEM_DYN>>>(x);
    stats_kernel<<<NPAD, 128>>>(gamma, beta);
    norm_kernel<<<416, 512>>>(out);
}

// round 16
// speedup vs baseline: 1.0817x; 1.0817x over previous
#include <cuda_runtime.h>
#include <cuda_bf16.h>
#include <cstdint>

typedef unsigned int u32;
typedef unsigned long long u64;

// Problem constants
#define B_ROWS 16384
#define DIM    768
#define ATTRS  51
#define NPAD   64
#define BN_EPS 1e-5f
#define GRID_M 128            // 16384 / 128 rows per CTA
#define NKS    48             // 768 / 16 k-steps
#define BP_U4  12288          // 48*8*32 uint4 entries {hi0,hi1,lo0,lo1}
#define SMEM_DYN 196608       // BP_U4 * 16 bytes
#define NJ     16             // wc1 j-splits
#define JCH    (DIM / NJ)     // 48 j's per wc1 block

// -------- device scratch --------
__device__ float g_wcp[NJ * NPAD * DIM];         // [q][a][k] j-partials (3 MB)
__device__ __align__(16) u32 g_bp[4 * BP_U4];    // packed B frags, uint4-interleaved
__device__ float g_z[B_ROWS * NPAD];             // logits (bias-free, padded)
__device__ float g_psum[GRID_M * NPAD];
__device__ float g_psq[GRID_M * NPAD];
__device__ float g_a[NPAD];                      // rstd*gamma
__device__ float g_b[NPAD];                      // beta - mean*rstd*gamma

// pack bf16x2, memory order (lo,hi)
__device__ __forceinline__ u32 bf16x2(float lo, float hi) {
    u32 r; asm("cvt.rn.bf16x2.f32 %0, %1, %2;" : "=r"(r) : "f"(hi), "f"(lo)); return r;
}
// split a float2 into bf16x2 hi + bf16x2 lo (residual)
__device__ __forceinline__ void split2(float2 v, u32& h, u32& l) {
    h = bf16x2(v.x, v.y);
    float f0 = __uint_as_float(h << 16);
    float f1 = __uint_as_float(h & 0xFFFF0000u);
    l = bf16x2(v.x - f0, v.y - f1);
}
// D += A(16x16 bf16) * B(16x8 bf16), fp32 accum
__device__ __forceinline__ void mma16816(float* c, const u32* a, u32 b0, u32 b1) {
    asm volatile(
        "mma.sync.aligned.m16n8k16.row.col.f32.bf16.bf16.f32 "
        "{%0,%1,%2,%3}, {%4,%5,%6,%7}, {%8,%9}, {%0,%1,%2,%3};"
        : "+f"(c[0]), "+f"(c[1]), "+f"(c[2]), "+f"(c[3])
        : "r"(a[0]), "r"(a[1]), "r"(a[2]), "r"(a[3]), "r"(b0), "r"(b1));
}
__device__ __forceinline__ u32 smem_u32(const void* p) {
    u32 a;
    asm("{ .reg .u64 t; cvta.to.shared.u64 t, %1; cvt.u32.u64 %0, t; }" : "=r"(a) : "l"(p));
    return a;
}
#define CP_ASYNC16(dst, src) \
    asm volatile("cp.async.cg.shared.global [%0], [%1], 16;" :: "r"(dst), "l"(src) : "memory")
#define CP_COMMIT() asm volatile("cp.async.commit_group;" ::: "memory")
#define CP_WAIT(n)  asm volatile("cp.async.wait_group %0;" :: "n"(n) : "memory")

// ============================================================
// wc1: j-partial Wc[a][k] over JCH j's.
// grid (6 k-blocks, 16 a-groups, NJ j-chunks) = 1536 blocks, 128 thr.
// ~40 warps/SM -> LDG latency hidden across warps. (Measured-best.)
// ============================================================
__global__ __launch_bounds__(128) void wc1_kernel(const float* __restrict__ W_embed,
                                                  const float* __restrict__ W_attr) {
    __shared__ float s_wa[4 * JCH];
    const int k  = blockIdx.x * 128 + threadIdx.x;
    const int a0 = blockIdx.y * 4;
    const int j0 = blockIdx.z * JCH;

    for (int i = threadIdx.x; i < 4 * JCH; i += 128) {
        int aa = i / JCH, j = i - aa * JCH;
        int a  = a0 + aa;
        s_wa[i] = (a < ATTRS) ? W_attr[a * DIM + j0 + j] : 0.0f;
    }
    __syncthreads();

    float acc0 = 0.f, acc1 = 0.f, acc2 = 0.f, acc3 = 0.f;
#pragma unroll 16
    for (int j = 0; j < JCH; ++j) {
        float we = W_embed[(size_t)(j0 + j) * DIM + k];
        acc0 = fmaf(s_wa[j          ], we, acc0);
        acc1 = fmaf(s_wa[JCH     + j], we, acc1);
        acc2 = fmaf(s_wa[2 * JCH + j], we, acc2);
        acc3 = fmaf(s_wa[3 * JCH + j], we, acc3);
    }
    float* dst = g_wcp + (size_t)blockIdx.z * NPAD * DIM;
    dst[(a0 + 0) * DIM + k] = acc0;
    dst[(a0 + 1) * DIM + k] = acc1;
    dst[(a0 + 2) * DIM + k] = acc2;
    dst[(a0 + 3) * DIM + k] = acc3;
}

// ============================================================
// wc2: combine NJ partials, split bf16 hi/lo, scatter into
// fused uint4 B-fragment layout: entry (ks,nt,lane) = {hi0,hi1,lo0,lo1}
// ============================================================
__global__ __launch_bounds__(256) void wc2_kernel() {
    int idx = blockIdx.x * 256 + threadIdx.x;     // 0..24575
    if (idx >= NPAD * DIM / 2) return;
    int n  = idx / 384;                           // 0..63
    int kp = idx - n * 384;
    int k  = kp * 2;
    size_t i0 = (size_t)n * DIM + k;
    const size_t S = (size_t)NPAD * DIM;
    float s0 = 0.f, s1 = 0.f;
#pragma unroll
    for (int q = 0; q < NJ; ++q) {
        s0 += g_wcp[q * S + i0];
        s1 += g_wcp[q * S + i0 + 1];
    }
    u32 h = bf16x2(s0, s1);
    float f0 = __uint_as_float(h << 16);
    float f1 = __uint_as_float(h & 0xFFFF0000u);
    u32 l = bf16x2(s0 - f0, s1 - f1);

    int ks = k >> 4;
    int hh = (k >> 3) & 1;
    int t  = (n & 7) * 4 + ((k & 7) >> 1);
    int nt = n >> 3;
    int o4 = ((ks * 8 + nt) * 32 + t) * 4;
    g_bp[o4 + hh]     = h;
    g_bp[o4 + 2 + hh] = l;
}

// ============================================================
// GEMM: z = x @ Wc^T via mma.sync bf16 hi/lo split (3 products).
// grid 128, 256 threads = 8 warps; warp w owns rows [w*16,+16).
// B staged via cp.async in 2 halves overlapped with compute.
// A from gmem fp32 at prefetch depth 4, split in registers.
// ============================================================
extern __shared__ __align__(16) char dsm[];

// one k-step of the mainloop
__device__ __forceinline__ void kstep(int ks, float2 (&pf)[4][4],
                                      const float* xr0, const float* xr8,
                                      const uint4* sb, int lane,
                                      float (&acc)[8][4]) {
    float2 c0 = pf[ks & 3][0], c1 = pf[ks & 3][1];
    float2 c2 = pf[ks & 3][2], c3 = pf[ks & 3][3];
    if (ks + 4 < NKS) {
        int kc = (ks + 4) * 16;
        pf[ks & 3][0] = *(const float2*)(xr0 + kc);
        pf[ks & 3][1] = *(const float2*)(xr0 + kc + 8);
        pf[ks & 3][2] = *(const float2*)(xr8 + kc);
        pf[ks & 3][3] = *(const float2*)(xr8 + kc + 8);
    }
    u32 ah[4], al[4];
    split2(c0, ah[0], al[0]);
    split2(c2, ah[1], al[1]);
    split2(c1, ah[2], al[2]);
    split2(c3, ah[3], al[3]);
    const uint4* bp = sb + ks * 256 + lane;
#pragma unroll
    for (int nt = 0; nt < 8; ++nt) {
        uint4 b = bp[nt * 32];
        mma16816(acc[nt], ah, b.x, b.y);
        mma16816(acc[nt], ah, b.z, b.w);
        mma16816(acc[nt], al, b.x, b.y);
    }
}

__global__ __launch_bounds__(256) void gemm_kernel(const float* __restrict__ x) {
    const int tid  = threadIdx.x;
    const int warp = tid >> 5, lane = tid & 31;

    // ---- stage packed B via cp.async: 2 halves of 6144 uint4 ----
    {
        const u32 sbase = smem_u32(dsm);
        const uint4* src = (const uint4*)g_bp;
#pragma unroll
        for (int i = 0; i < 24; ++i) {
            int idx = tid + i * 256;
            CP_ASYNC16(sbase + idx * 16, src + idx);
        }
        CP_COMMIT();
#pragma unroll
        for (int i = 0; i < 24; ++i) {
            int idx = 6144 + tid + i * 256;
            CP_ASYNC16(sbase + idx * 16, src + idx);
        }
        CP_COMMIT();
    }
    const uint4* sb = (const uint4*)dsm;   // [(ks*8+nt)*32 + lane] = {hi0,hi1,lo0,lo1}

    const int r0 = blockIdx.x * 128 + warp * 16 + (lane >> 2);
    const float* xr0 = x + (size_t)r0 * DIM + (lane & 3) * 2;
    const float* xr8 = xr0 + 8 * DIM;

    float acc[8][4];
#pragma unroll
    for (int i = 0; i < 8; ++i)
#pragma unroll
        for (int j = 0; j < 4; ++j) acc[i][j] = 0.0f;

    // A fragment prefetch, depth 4
    float2 pf[4][4];
#pragma unroll
    for (int p = 0; p < 4; ++p) {
        int kc = p * 16;
        pf[p][0] = *(const float2*)(xr0 + kc);
        pf[p][1] = *(const float2*)(xr0 + kc + 8);
        pf[p][2] = *(const float2*)(xr8 + kc);
        pf[p][3] = *(const float2*)(xr8 + kc + 8);
    }

    CP_WAIT(1);            // first half of B resident
    __syncthreads();

#pragma unroll 4
    for (int ks = 0; ks < 24; ++ks)
        kstep(ks, pf, xr0, xr8, sb, lane, acc);

    CP_WAIT(0);            // second half of B resident
    __syncthreads();

#pragma unroll 4
    for (int ks = 24; ks < NKS; ++ks)
        kstep(ks, pf, xr0, xr8, sb, lane, acc);

    // ---- epilogue: store z + BN partials (reuse smem) ----
    __syncthreads();
    float* ssum = (float*)dsm;
    float* ssq  = ssum + NPAD;
    if (tid < 2 * NPAD) ssum[tid] = 0.0f;
    __syncthreads();

    float* zr = g_z + (size_t)r0 * NPAD;
#pragma unroll
    for (int nt = 0; nt < 8; ++nt) {
        int n0 = nt * 8 + (lane & 3) * 2;
        *(float2*)(zr + n0)            = make_float2(acc[nt][0], acc[nt][1]);
        *(float2*)(zr + 8 * NPAD + n0) = make_float2(acc[nt][2], acc[nt][3]);
        float s0 = acc[nt][0] + acc[nt][2];
        float s1 = acc[nt][1] + acc[nt][3];
        float q0 = fmaf(acc[nt][0], acc[nt][0], acc[nt][2] * acc[nt][2]);
        float q1 = fmaf(acc[nt][1], acc[nt][1], acc[nt][3] * acc[nt][3]);
#pragma unroll
        for (int m = 4; m <= 16; m <<= 1) {
            s0 += __shfl_xor_sync(0xffffffffu, s0, m);
            s1 += __shfl_xor_sync(0xffffffffu, s1, m);
            q0 += __shfl_xor_sync(0xffffffffu, q0, m);
            q1 += __shfl_xor_sync(0xffffffffu, q1, m);
        }
        if (lane < 4) {
            atomicAdd(&ssum[n0], s0);     atomicAdd(&ssum[n0 + 1], s1);
            atomicAdd(&ssq[n0], q0);      atomicAdd(&ssq[n0 + 1], q1);
        }
    }
    __syncthreads();
    if (tid < NPAD) {
        g_psum[blockIdx.x * NPAD + tid] = ssum[tid];
        g_psq[blockIdx.x * NPAD + tid]  = ssq[tid];
    }
}

// ============================================================
// stats: one block per column n (64 blocks, 128 threads)
// ============================================================
__global__ __launch_bounds__(128) void stats_kernel(const float* __restrict__ gamma,
                                                    const float* __restrict__ beta) {
    __shared__ float ss[4], sq[4];
    const int n = blockIdx.x;           // 0..63
    const int t = threadIdx.x;          // 0..127
    float s = g_psum[t * NPAD + n];
    float q = g_psq[t * NPAD + n];
#pragma unroll
    for (int m = 16; m >= 1; m >>= 1) {
        s += __shfl_xor_sync(0xffffffffu, s, m);
        q += __shfl_xor_sync(0xffffffffu, q, m);
    }
    if ((t & 31) == 0) { ss[t >> 5] = s; sq[t >> 5] = q; }
    __syncthreads();
    if (t == 0) {
        float S = ss[0] + ss[1] + ss[2] + ss[3];
        float Q = sq[0] + sq[1] + sq[2] + sq[3];
        const float inv = 1.0f / (float)B_ROWS;
        float mean = S * inv;
        float var  = Q * inv - mean * mean;
        float rstd = rsqrtf(var + BN_EPS);
        float gm = (n < ATTRS) ? gamma[n] : 0.0f;
        float bt = (n < ATTRS) ? beta[n]  : 0.0f;
        float a = rstd * gm;
        g_a[n] = a;
        g_b[n] = bt - mean * a;
    }
}

// ============================================================
// norm: y = z*a[n] + b[n] -> d_out [B,51]
// 204*512*8 = 835584 = 16384*51 exactly
// ============================================================
__global__ __launch_bounds__(512) void norm_kernel(float* __restrict__ out) {
    const int b0 = blockIdx.x * 512 + threadIdx.x;
#pragma unroll
    for (int i = 0; i < 8; ++i) {
        int idx = b0 + i * 104448;
        int row = idx / ATTRS;
        int n   = idx - row * ATTRS;
        out[idx] = fmaf(g_z[(size_t)row * NPAD + n], g_a[n], g_b[n]);
    }
}

// ============================================================
extern "C" void kernel_launch(void* const* d_in, const int* in_sizes, int n_in,
                              void* d_out, int out_size) {
    const float* x       = (const float*)d_in[0];
    const float* W_embed = (const float*)d_in[1];
    // d_in[2] = b_embed  (cancelled exactly by BatchNorm mean-subtraction)
    const float* W_attr  = (const float*)d_in[3];
    // d_in[4] = b_attr   (cancelled exactly by BatchNorm mean-subtraction)
    const float* gamma   = (const float*)d_in[5];
    const float* beta    = (const float*)d_in[6];
    float* out = (float*)d_out;

    cudaFuncSetAttribute(gemm_kernel, cudaFuncAttributeMaxDynamicSharedMemorySize, SMEM_DYN);

    wc1_kernel<<<dim3(6, 16, NJ), 128>>>(W_embed, W_attr);
    wc2_kernel<<<96, 256>>>();
    gemm_kernel<<<GRID_M, 256, SMEM_DYN>>>(x);
    stats_kernel<<<NPAD, 128>>>(gamma, beta);
    norm_kernel<<<204, 512>>>(out);
}

// round 17
// speedup vs baseline: 1.2233x; 1.1309x over previous
#include <cuda_runtime.h>
#include <cuda_bf16.h>
#include <cstdint>

typedef unsigned int u32;
typedef unsigned long long u64;

// Problem constants
#define B_ROWS 16384
#define DIM    768
#define ATTRS  51
#define NPAD   64
#define BN_EPS 1e-5f
#define GRID_M 128            // 16384 / 128 rows per CTA
#define NKS    48             // 768 / 16 k-steps
#define BP_U4  12288          // 48*8*32 uint4 entries {hi0,hi1,lo0,lo1}
#define SMEM_DYN 196608       // BP_U4 * 16 bytes
#define NJ     16             // wc1 j-splits
#define JCH    (DIM / NJ)     // 48 j's per wc1 block

// -------- device scratch --------
__device__ float g_wcp[NJ * NPAD * DIM];         // [q][a][k] j-partials (3 MB)
__device__ __align__(16) u32 g_bp[4 * BP_U4];    // packed B frags, uint4-interleaved
__device__ float g_z[B_ROWS * NPAD];             // logits (bias-free, padded)
__device__ float g_psum[GRID_M * NPAD];
__device__ float g_psq[GRID_M * NPAD];

// pack bf16x2, memory order (lo,hi)
__device__ __forceinline__ u32 bf16x2(float lo, float hi) {
    u32 r; asm("cvt.rn.bf16x2.f32 %0, %1, %2;" : "=r"(r) : "f"(hi), "f"(lo)); return r;
}
// split a float2 into bf16x2 hi + bf16x2 lo (residual)
__device__ __forceinline__ void split2(float2 v, u32& h, u32& l) {
    h = bf16x2(v.x, v.y);
    float f0 = __uint_as_float(h << 16);
    float f1 = __uint_as_float(h & 0xFFFF0000u);
    l = bf16x2(v.x - f0, v.y - f1);
}
// D += A(16x16 bf16) * B(16x8 bf16), fp32 accum
__device__ __forceinline__ void mma16816(float* c, const u32* a, u32 b0, u32 b1) {
    asm volatile(
        "mma.sync.aligned.m16n8k16.row.col.f32.bf16.bf16.f32 "
        "{%0,%1,%2,%3}, {%4,%5,%6,%7}, {%8,%9}, {%0,%1,%2,%3};"
        : "+f"(c[0]), "+f"(c[1]), "+f"(c[2]), "+f"(c[3])
        : "r"(a[0]), "r"(a[1]), "r"(a[2]), "r"(a[3]), "r"(b0), "r"(b1));
}
__device__ __forceinline__ u32 smem_u32(const void* p) {
    u32 a;
    asm("{ .reg .u64 t; cvta.to.shared.u64 t, %1; cvt.u32.u64 %0, t; }" : "=r"(a) : "l"(p));
    return a;
}
#define CP_ASYNC16(dst, src) \
    asm volatile("cp.async.cg.shared.global [%0], [%1], 16;" :: "r"(dst), "l"(src) : "memory")
#define CP_COMMIT() asm volatile("cp.async.commit_group;" ::: "memory")
#define CP_WAIT(n)  asm volatile("cp.async.wait_group %0;" :: "n"(n) : "memory")

// ============================================================
// wc1: j-partial Wc[a][k] over JCH j's.
// grid (6 k-blocks, 16 a-groups, NJ j-chunks) = 1536 blocks, 128 thr.
// ~40 warps/SM -> LDG latency hidden across warps. (Measured-best.)
// ============================================================
__global__ __launch_bounds__(128) void wc1_kernel(const float* __restrict__ W_embed,
                                                  const float* __restrict__ W_attr) {
    __shared__ float s_wa[4 * JCH];
    const int k  = blockIdx.x * 128 + threadIdx.x;
    const int a0 = blockIdx.y * 4;
    const int j0 = blockIdx.z * JCH;

    for (int i = threadIdx.x; i < 4 * JCH; i += 128) {
        int aa = i / JCH, j = i - aa * JCH;
        int a  = a0 + aa;
        s_wa[i] = (a < ATTRS) ? W_attr[a * DIM + j0 + j] : 0.0f;
    }
    __syncthreads();

    float acc0 = 0.f, acc1 = 0.f, acc2 = 0.f, acc3 = 0.f;
#pragma unroll 16
    for (int j = 0; j < JCH; ++j) {
        float we = W_embed[(size_t)(j0 + j) * DIM + k];
        acc0 = fmaf(s_wa[j          ], we, acc0);
        acc1 = fmaf(s_wa[JCH     + j], we, acc1);
        acc2 = fmaf(s_wa[2 * JCH + j], we, acc2);
        acc3 = fmaf(s_wa[3 * JCH + j], we, acc3);
    }
    float* dst = g_wcp + (size_t)blockIdx.z * NPAD * DIM;
    dst[(a0 + 0) * DIM + k] = acc0;
    dst[(a0 + 1) * DIM + k] = acc1;
    dst[(a0 + 2) * DIM + k] = acc2;
    dst[(a0 + 3) * DIM + k] = acc3;
}

// ============================================================
// wc2: combine NJ partials, split bf16 hi/lo, scatter into
// fused uint4 B-fragment layout: entry (ks,nt,lane) = {hi0,hi1,lo0,lo1}
// ============================================================
__global__ __launch_bounds__(256) void wc2_kernel() {
    int idx = blockIdx.x * 256 + threadIdx.x;     // 0..24575
    if (idx >= NPAD * DIM / 2) return;
    int n  = idx / 384;                           // 0..63
    int kp = idx - n * 384;
    int k  = kp * 2;
    size_t i0 = (size_t)n * DIM + k;
    const size_t S = (size_t)NPAD * DIM;
    float s0 = 0.f, s1 = 0.f;
#pragma unroll
    for (int q = 0; q < NJ; ++q) {
        s0 += g_wcp[q * S + i0];
        s1 += g_wcp[q * S + i0 + 1];
    }
    u32 h = bf16x2(s0, s1);
    float f0 = __uint_as_float(h << 16);
    float f1 = __uint_as_float(h & 0xFFFF0000u);
    u32 l = bf16x2(s0 - f0, s1 - f1);

    int ks = k >> 4;
    int hh = (k >> 3) & 1;
    int t  = (n & 7) * 4 + ((k & 7) >> 1);
    int nt = n >> 3;
    int o4 = ((ks * 8 + nt) * 32 + t) * 4;
    g_bp[o4 + hh]     = h;
    g_bp[o4 + 2 + hh] = l;
}

// ============================================================
// GEMM: z = x @ Wc^T via mma.sync bf16 hi/lo split (3 products).
// grid 128, 256 threads = 8 warps; warp w owns rows [w*16,+16).
// B staged via cp.async in 2 halves; A-prefetch LDGs issued
// between the halves so the x DRAM stream starts immediately.
// ============================================================
extern __shared__ __align__(16) char dsm[];

// one k-step of the mainloop
__device__ __forceinline__ void kstep(int ks, float2 (&pf)[4][4],
                                      const float* xr0, const float* xr8,
                                      const uint4* sb, int lane,
                                      float (&acc)[8][4]) {
    float2 c0 = pf[ks & 3][0], c1 = pf[ks & 3][1];
    float2 c2 = pf[ks & 3][2], c3 = pf[ks & 3][3];
    if (ks + 4 < NKS) {
        int kc = (ks + 4) * 16;
        pf[ks & 3][0] = *(const float2*)(xr0 + kc);
        pf[ks & 3][1] = *(const float2*)(xr0 + kc + 8);
        pf[ks & 3][2] = *(const float2*)(xr8 + kc);
        pf[ks & 3][3] = *(const float2*)(xr8 + kc + 8);
    }
    u32 ah[4], al[4];
    split2(c0, ah[0], al[0]);
    split2(c2, ah[1], al[1]);
    split2(c1, ah[2], al[2]);
    split2(c3, ah[3], al[3]);
    const uint4* bp = sb + ks * 256 + lane;
#pragma unroll
    for (int nt = 0; nt < 8; ++nt) {
        uint4 b = bp[nt * 32];
        mma16816(acc[nt], ah, b.x, b.y);
        mma16816(acc[nt], ah, b.z, b.w);
        mma16816(acc[nt], al, b.x, b.y);
    }
}

__global__ __launch_bounds__(256) void gemm_kernel(const float* __restrict__ x) {
    const int tid  = threadIdx.x;
    const int warp = tid >> 5, lane = tid & 31;

    const int r0 = blockIdx.x * 128 + warp * 16 + (lane >> 2);
    const float* xr0 = x + (size_t)r0 * DIM + (lane & 3) * 2;
    const float* xr8 = xr0 + 8 * DIM;

    // ---- first half of B via cp.async ----
    const u32 sbase = smem_u32(dsm);
    {
        const uint4* src = (const uint4*)g_bp;
#pragma unroll
        for (int i = 0; i < 24; ++i) {
            int idx = tid + i * 256;
            CP_ASYNC16(sbase + idx * 16, src + idx);
        }
        CP_COMMIT();
    }

    // ---- A fragment prefetch, depth 4 (starts x DRAM stream now) ----
    float2 pf[4][4];
#pragma unroll
    for (int p = 0; p < 4; ++p) {
        int kc = p * 16;
        pf[p][0] = *(const float2*)(xr0 + kc);
        pf[p][1] = *(const float2*)(xr0 + kc + 8);
        pf[p][2] = *(const float2*)(xr8 + kc);
        pf[p][3] = *(const float2*)(xr8 + kc + 8);
    }

    // ---- second half of B via cp.async ----
    {
        const uint4* src = (const uint4*)g_bp;
#pragma unroll
        for (int i = 0; i < 24; ++i) {
            int idx = 6144 + tid + i * 256;
            CP_ASYNC16(sbase + idx * 16, src + idx);
        }
        CP_COMMIT();
    }
    const uint4* sb = (const uint4*)dsm;   // [(ks*8+nt)*32 + lane] = {hi0,hi1,lo0,lo1}

    float acc[8][4];
#pragma unroll
    for (int i = 0; i < 8; ++i)
#pragma unroll
        for (int j = 0; j < 4; ++j) acc[i][j] = 0.0f;

    CP_WAIT(1);            // first half of B resident
    __syncthreads();

#pragma unroll 4
    for (int ks = 0; ks < 24; ++ks)
        kstep(ks, pf, xr0, xr8, sb, lane, acc);

    CP_WAIT(0);            // second half of B resident
    __syncthreads();

#pragma unroll 4
    for (int ks = 24; ks < NKS; ++ks)
        kstep(ks, pf, xr0, xr8, sb, lane, acc);

    // ---- epilogue: store z + BN partials (reuse smem) ----
    __syncthreads();
    float* ssum = (float*)dsm;
    float* ssq  = ssum + NPAD;
    if (tid < 2 * NPAD) ssum[tid] = 0.0f;
    __syncthreads();

    float* zr = g_z + (size_t)r0 * NPAD;
#pragma unroll
    for (int nt = 0; nt < 8; ++nt) {
        int n0 = nt * 8 + (lane & 3) * 2;
        *(float2*)(zr + n0)            = make_float2(acc[nt][0], acc[nt][1]);
        *(float2*)(zr + 8 * NPAD + n0) = make_float2(acc[nt][2], acc[nt][3]);
        float s0 = acc[nt][0] + acc[nt][2];
        float s1 = acc[nt][1] + acc[nt][3];
        float q0 = fmaf(acc[nt][0], acc[nt][0], acc[nt][2] * acc[nt][2]);
        float q1 = fmaf(acc[nt][1], acc[nt][1], acc[nt][3] * acc[nt][3]);
#pragma unroll
        for (int m = 4; m <= 16; m <<= 1) {
            s0 += __shfl_xor_sync(0xffffffffu, s0, m);
            s1 += __shfl_xor_sync(0xffffffffu, s1, m);
            q0 += __shfl_xor_sync(0xffffffffu, q0, m);
            q1 += __shfl_xor_sync(0xffffffffu, q1, m);
        }
        if (lane < 4) {
            atomicAdd(&ssum[n0], s0);     atomicAdd(&ssum[n0 + 1], s1);
            atomicAdd(&ssq[n0], q0);      atomicAdd(&ssq[n0 + 1], q1);
        }
    }
    __syncthreads();
    if (tid < NPAD) {
        g_psum[blockIdx.x * NPAD + tid] = ssum[tid];
        g_psq[blockIdx.x * NPAD + tid]  = ssq[tid];
    }
}

// ============================================================
// normstats: fused stats + normalize. grid 128 x 512 threads.
// Each block redundantly reduces the 128x64 partials (L2-hot)
// into smem a[n],b[n], then normalizes its 128 rows -> d_out.
// ============================================================
__global__ __launch_bounds__(512) void normstats_kernel(const float* __restrict__ gamma,
                                                        const float* __restrict__ beta,
                                                        float* __restrict__ out) {
    __shared__ float rs[8][NPAD], rq[8][NPAD];
    __shared__ float sa[NPAD], sb[NPAD];
    const int t = threadIdx.x;
    const int n = t & 63, g = t >> 6;    // 64 cols x 8 groups

    float s = 0.f, q = 0.f;
#pragma unroll
    for (int b = g; b < GRID_M; b += 8) {
        s += g_psum[b * NPAD + n];
        q += g_psq[b * NPAD + n];
    }
    rs[g][n] = s; rq[g][n] = q;
    __syncthreads();
    if (t < NPAD) {
        float S = 0.f, Q = 0.f;
#pragma unroll
        for (int i = 0; i < 8; ++i) { S += rs[i][n]; Q += rq[i][n]; }
        const float inv = 1.0f / (float)B_ROWS;
        float mean = S * inv;
        float var  = Q * inv - mean * mean;
        float rstd = rsqrtf(var + BN_EPS);
        float gm = (n < ATTRS) ? gamma[n] : 0.0f;
        float bt = (n < ATTRS) ? beta[n]  : 0.0f;
        float a = rstd * gm;
        sa[n] = a;
        sb[n] = bt - mean * a;
    }
    __syncthreads();

    // normalize rows [blk*128, +128): 128 rows x 13 quads = 1664 quads
    const int row0 = blockIdx.x * 128;
#pragma unroll
    for (int i = 0; i < 4; ++i) {
        int idx = t + i * 512;
        if (idx < 128 * 13) {
            int r  = idx / 13;
            int qd = idx - r * 13;
            int n0 = qd * 4;
            int row = row0 + r;
            float4 z = *(const float4*)(g_z + (size_t)row * NPAD + n0);
            float* o = out + (size_t)row * ATTRS + n0;
            o[0] = fmaf(z.x, sa[n0],     sb[n0]);
            o[1] = fmaf(z.y, sa[n0 + 1], sb[n0 + 1]);
            o[2] = fmaf(z.z, sa[n0 + 2], sb[n0 + 2]);
            if (qd < 12) o[3] = fmaf(z.w, sa[n0 + 3], sb[n0 + 3]);
        }
    }
}

// ============================================================
extern "C" void kernel_launch(void* const* d_in, const int* in_sizes, int n_in,
                              void* d_out, int out_size) {
    const float* x       = (const float*)d_in[0];
    const float* W_embed = (const float*)d_in[1];
    // d_in[2] = b_embed  (cancelled exactly by BatchNorm mean-subtraction)
    const float* W_attr  = (const float*)d_in[3];
    // d_in[4] = b_attr   (cancelled exactly by BatchNorm mean-subtraction)
    const float* gamma   = (const float*)d_in[5];
    const float* beta    = (const float*)d_in[6];
    float* out = (float*)d_out;

    cudaFuncSetAttribute(gemm_kernel, cudaFuncAttributeMaxDynamicSharedMemorySize, SMEM_DYN);

    wc1_kernel<<<dim3(6, 16, NJ), 128>>>(W_embed, W_attr);
    wc2_kernel<<<96, 256>>>();
    gemm_kernel<<<GRID_M, 256, SMEM_DYN>>>(x);
    normstats_kernel<<<GRID_M, 512>>>(gamma, beta, out);
}